// round 3
// baseline (speedup 1.0000x reference)
#include <cuda_runtime.h>
#include <cstdint>

#define N_CELLS 50000
#define N_GENES 2000
#define HIDDEN 128
#define E_FULL 800000
#define E_PRUNED 400000

// ---------------- device scratch (allocation-free per harness rules) ----------------
__device__ float g_h[(size_t)N_CELLS * HIDDEN];       // 25.6 MB
__device__ float g_hcat[(size_t)N_CELLS * 512];       // 102.4 MB: [hsF | hdF | hsP | hdP]
__device__ float g_wcat[128 * 512];                   // packed [gf_wsrc|gf_wdst|gp_wsrc|gp_wdst]
__device__ int g_cntF[N_CELLS], g_cntP[N_CELLS];
__device__ int g_offF[N_CELLS + 1], g_offP[N_CELLS + 1];
__device__ int g_curF[N_CELLS], g_curP[N_CELLS];
__device__ int g_eidF[E_FULL], g_eidP[E_PRUNED];

// ---------------- small helpers ----------------
__device__ __forceinline__ float lo2(unsigned long long v) {
    return __uint_as_float((unsigned)(v & 0xffffffffull));
}
__device__ __forceinline__ float hi2(unsigned long long v) {
    return __uint_as_float((unsigned)(v >> 32));
}

// ---------------- pack W concat ----------------
__global__ void pack_wcat(const float* __restrict__ a, const float* __restrict__ b,
                          const float* __restrict__ c, const float* __restrict__ d) {
    int i = blockIdx.x * blockDim.x + threadIdx.x;
    if (i >= 128 * 512) return;
    int k = i >> 9;
    int j = i & 511;
    const float* s = (j < 128) ? a : (j < 256) ? b : (j < 384) ? c : d;
    g_wcat[i] = s[k * 128 + (j & 127)];
}

__global__ void zero_counts() {
    int i = blockIdx.x * blockDim.x + threadIdx.x;
    if (i < N_CELLS) { g_cntF[i] = 0; g_cntP[i] = 0; }
}

__global__ void count_edges(const int* __restrict__ idx, int E, int which) {
    int e = blockIdx.x * blockDim.x + threadIdx.x;
    if (e >= E) return;
    int dst = idx[E + e];
    atomicAdd(which ? &g_cntP[dst] : &g_cntF[dst], 1);
}

__global__ void scan_counts(int which) {
    const int n = N_CELLS;
    int* cnt = which ? g_cntP : g_cntF;
    int* off = which ? g_offP : g_offF;
    int* cur = which ? g_curP : g_curF;
    __shared__ int sh[1024];
    __shared__ int carry;
    int tid = threadIdx.x;
    if (tid == 0) carry = 0;
    __syncthreads();
    for (int base = 0; base < n; base += 1024) {
        int idx = base + tid;
        int v = (idx < n) ? cnt[idx] : 0;
        sh[tid] = v;
        __syncthreads();
        #pragma unroll
        for (int o = 1; o < 1024; o <<= 1) {
            int t = (tid >= o) ? sh[tid - o] : 0;
            __syncthreads();
            sh[tid] += t;
            __syncthreads();
        }
        int c = carry;
        if (idx < n) {
            int excl = c + sh[tid] - v;
            off[idx] = excl;
            cur[idx] = excl;
        }
        __syncthreads();
        if (tid == 0) carry = c + sh[1023];
        __syncthreads();
    }
    if (tid == 0) off[n] = carry;
}

__global__ void scatter_edges(const int* __restrict__ idx, int E, int which) {
    int e = blockIdx.x * blockDim.x + threadIdx.x;
    if (e >= E) return;
    int dst = idx[E + e];
    int pos = atomicAdd(which ? &g_curP[dst] : &g_curF[dst], 1);
    (which ? g_eidP : g_eidF)[pos] = e;
}

// ---------------- fp32 GEMM with packed f32x2 FFMA ----------------
// C[M,N] = A[M,K] @ B[K,N] (+ bias). N multiple of 128, K multiple of 16.
// a_sel: 0 -> Aext, 1 -> g_h ; b_sel: 0 -> Bext, 1 -> g_wcat ; c_sel: 0 -> g_h, 1 -> g_hcat
__global__ void __launch_bounds__(256) gemm_f32(const float* __restrict__ Aext,
                                                const float* __restrict__ Bext,
                                                const float* __restrict__ bias,
                                                int a_sel, int b_sel, int c_sel,
                                                int M, int N, int K) {
    const int BM = 128, BN = 128, BK = 16, TM = 8, TN = 8;
    __shared__ __align__(16) float As[BK][BM];
    __shared__ __align__(16) float Bs[BK][BN];

    const float* A = a_sel ? g_h : Aext;
    const float* B = b_sel ? g_wcat : Bext;
    float* C = c_sel ? g_hcat : g_h;

    int tid = threadIdx.x;
    int tx = tid & 15;       // N micro-tile
    int ty = tid >> 4;       // M micro-tile
    long rowBase = (long)blockIdx.y * BM;
    int colBase = blockIdx.x * BN;

    int aRow = tid >> 2;         // 0..63
    int aCol = (tid & 3) * 4;    // 0,4,8,12
    int bRow = tid >> 5;         // 0..7
    int bCol = (tid & 31) * 4;   // 0..124

    unsigned long long acc[TM][TN / 2];
    #pragma unroll
    for (int i = 0; i < TM; i++)
        #pragma unroll
        for (int j = 0; j < TN / 2; j++) acc[i][j] = 0ull;

    for (int k0 = 0; k0 < K; k0 += BK) {
        #pragma unroll
        for (int i = 0; i < 2; i++) {
            int r = aRow + i * 64;
            long gr = rowBase + r;
            float4 v = make_float4(0.f, 0.f, 0.f, 0.f);
            if (gr < M) v = __ldg(reinterpret_cast<const float4*>(A + gr * K + k0 + aCol));
            As[aCol + 0][r] = v.x;
            As[aCol + 1][r] = v.y;
            As[aCol + 2][r] = v.z;
            As[aCol + 3][r] = v.w;
        }
        #pragma unroll
        for (int i = 0; i < 2; i++) {
            int r = bRow + i * 8;
            *reinterpret_cast<float4*>(&Bs[r][bCol]) =
                __ldg(reinterpret_cast<const float4*>(B + (long)(k0 + r) * N + colBase + bCol));
        }
        __syncthreads();
        #pragma unroll
        for (int kk = 0; kk < BK; kk++) {
            unsigned long long ra2[TM];
            unsigned long long rb2[TN / 2];
            #pragma unroll
            for (int i = 0; i < TM; i++) {
                unsigned u = __float_as_uint(As[kk][ty * TM + i]);
                asm("mov.b64 %0, {%1,%1};" : "=l"(ra2[i]) : "r"(u));
            }
            #pragma unroll
            for (int j = 0; j < TN / 2; j++)
                rb2[j] = *reinterpret_cast<const unsigned long long*>(&Bs[kk][tx * TN + 2 * j]);
            #pragma unroll
            for (int i = 0; i < TM; i++)
                #pragma unroll
                for (int j = 0; j < TN / 2; j++)
                    asm("fma.rn.f32x2 %0, %1, %2, %0;"
                        : "+l"(acc[i][j]) : "l"(ra2[i]), "l"(rb2[j]));
        }
        __syncthreads();
    }

    #pragma unroll
    for (int i = 0; i < TM; i++) {
        long gr = rowBase + ty * TM + i;
        if (gr >= M) continue;
        int col = colBase + tx * TN;
        float f[8];
        #pragma unroll
        for (int j = 0; j < TN / 2; j++) {
            f[2 * j] = lo2(acc[i][j]);
            f[2 * j + 1] = hi2(acc[i][j]);
        }
        if (bias) {
            #pragma unroll
            for (int t = 0; t < 8; t++) f[t] += __ldg(&bias[col + t]);
        }
        *reinterpret_cast<float4*>(C + gr * N + col) = make_float4(f[0], f[1], f[2], f[3]);
        *reinterpret_cast<float4*>(C + gr * N + col + 4) = make_float4(f[4], f[5], f[6], f[7]);
    }
}

// ---------------- fused GAT aggregation (both graphs) + combine + ELU + LayerNorm ----------------
// One warp per destination node. Single-pass online softmax (no max subtraction; logits bounded).
__global__ void __launch_bounds__(256) gat_finalize(
    const int* __restrict__ idxF, const float* __restrict__ wF,
    const int* __restrict__ idxP, const float* __restrict__ wP,
    const float* __restrict__ alpha_p,
    const float* __restrict__ weF, const float* __restrict__ atF, const float* __restrict__ biF,
    const float* __restrict__ weP, const float* __restrict__ atP, const float* __restrict__ biP,
    const float* __restrict__ lnS, const float* __restrict__ lnB,
    float* __restrict__ out) {
    int gw = (blockIdx.x * blockDim.x + threadIdx.x) >> 5;
    int lane = threadIdx.x & 31;
    if (gw >= N_CELLS) return;

    const float4* hc = reinterpret_cast<const float4*>(g_hcat);
    size_t row = (size_t)gw * 128;  // in float4 units (512 floats per row)

    float4 hdF = __ldg(hc + row + 32 + lane);
    float4 hdP = __ldg(hc + row + 96 + lane);
    float4 vweF = __ldg(reinterpret_cast<const float4*>(weF) + lane);
    float4 vatF = __ldg(reinterpret_cast<const float4*>(atF) + lane);
    float4 vweP = __ldg(reinterpret_cast<const float4*>(weP) + lane);
    float4 vatP = __ldg(reinterpret_cast<const float4*>(atP) + lane);

    float4 accF = make_float4(0.f, 0.f, 0.f, 0.f);
    float denF = 0.f;
    {
        int s = g_offF[gw], t = g_offF[gw + 1];
        for (int i = s; i < t; i++) {
            int e = g_eidF[i];
            int src = __ldg(&idxF[e]);
            float we = __ldg(&wF[e]);
            float4 hs = __ldg(hc + (size_t)src * 128 + lane);
            float4 z;
            z.x = fmaf(we, vweF.x, hs.x + hdF.x);
            z.y = fmaf(we, vweF.y, hs.y + hdF.y);
            z.z = fmaf(we, vweF.z, hs.z + hdF.z);
            z.w = fmaf(we, vweF.w, hs.w + hdF.w);
            z.x = fmaxf(z.x, 0.2f * z.x);
            z.y = fmaxf(z.y, 0.2f * z.y);
            z.z = fmaxf(z.z, 0.2f * z.z);
            z.w = fmaxf(z.w, 0.2f * z.w);
            float p = z.x * vatF.x + z.y * vatF.y + z.z * vatF.z + z.w * vatF.w;
            p += __shfl_xor_sync(0xffffffffu, p, 1);
            p += __shfl_xor_sync(0xffffffffu, p, 2);
            p += __shfl_xor_sync(0xffffffffu, p, 4);
            float ex = __expf(p);
            denF += ex;
            accF.x = fmaf(ex, hs.x, accF.x);
            accF.y = fmaf(ex, hs.y, accF.y);
            accF.z = fmaf(ex, hs.z, accF.z);
            accF.w = fmaf(ex, hs.w, accF.w);
        }
    }

    float4 accP = make_float4(0.f, 0.f, 0.f, 0.f);
    float denP = 0.f;
    {
        int s = g_offP[gw], t = g_offP[gw + 1];
        for (int i = s; i < t; i++) {
            int e = g_eidP[i];
            int src = __ldg(&idxP[e]);
            float we = __ldg(&wP[e]);
            float4 hs = __ldg(hc + (size_t)src * 128 + 64 + lane);
            float4 z;
            z.x = fmaf(we, vweP.x, hs.x + hdP.x);
            z.y = fmaf(we, vweP.y, hs.y + hdP.y);
            z.z = fmaf(we, vweP.z, hs.z + hdP.z);
            z.w = fmaf(we, vweP.w, hs.w + hdP.w);
            z.x = fmaxf(z.x, 0.2f * z.x);
            z.y = fmaxf(z.y, 0.2f * z.y);
            z.z = fmaxf(z.z, 0.2f * z.z);
            z.w = fmaxf(z.w, 0.2f * z.w);
            float p = z.x * vatP.x + z.y * vatP.y + z.z * vatP.z + z.w * vatP.w;
            p += __shfl_xor_sync(0xffffffffu, p, 1);
            p += __shfl_xor_sync(0xffffffffu, p, 2);
            p += __shfl_xor_sync(0xffffffffu, p, 4);
            float ex = __expf(p);
            denP += ex;
            accP.x = fmaf(ex, hs.x, accP.x);
            accP.y = fmaf(ex, hs.y, accP.y);
            accP.z = fmaf(ex, hs.z, accP.z);
            accP.w = fmaf(ex, hs.w, accP.w);
        }
    }

    float alpha = __ldg(alpha_p);
    float rdF = 1.f / (denF + 1e-16f);
    float rdP = 1.f / (denP + 1e-16f);
    float4 bF = __ldg(reinterpret_cast<const float4*>(biF) + lane);
    float4 bP = __ldg(reinterpret_cast<const float4*>(biP) + lane);
    float a1 = 1.f - alpha;

    float4 r;
    r.x = a1 * (accF.x * rdF + bF.x) + alpha * (accP.x * rdP + bP.x);
    r.y = a1 * (accF.y * rdF + bF.y) + alpha * (accP.y * rdP + bP.y);
    r.z = a1 * (accF.z * rdF + bF.z) + alpha * (accP.z * rdP + bP.z);
    r.w = a1 * (accF.w * rdF + bF.w) + alpha * (accP.w * rdP + bP.w);

    // ELU
    r.x = r.x > 0.f ? r.x : expm1f(r.x);
    r.y = r.y > 0.f ? r.y : expm1f(r.y);
    r.z = r.z > 0.f ? r.z : expm1f(r.z);
    r.w = r.w > 0.f ? r.w : expm1f(r.w);

    // LayerNorm over 128 (warp allreduce)
    float sum = r.x + r.y + r.z + r.w;
    #pragma unroll
    for (int o = 16; o >= 1; o >>= 1) sum += __shfl_xor_sync(0xffffffffu, sum, o);
    float mu = sum * (1.f / 128.f);
    float4 d;
    d.x = r.x - mu; d.y = r.y - mu; d.z = r.z - mu; d.w = r.w - mu;
    float sq = d.x * d.x + d.y * d.y + d.z * d.z + d.w * d.w;
    #pragma unroll
    for (int o = 16; o >= 1; o >>= 1) sq += __shfl_xor_sync(0xffffffffu, sq, o);
    float rstd = rsqrtf(sq * (1.f / 128.f) + 1e-6f);
    float4 s4 = __ldg(reinterpret_cast<const float4*>(lnS) + lane);
    float4 b4 = __ldg(reinterpret_cast<const float4*>(lnB) + lane);
    float4 o;
    o.x = d.x * rstd * s4.x + b4.x;
    o.y = d.y * rstd * s4.y + b4.y;
    o.z = d.z * rstd * s4.z + b4.z;
    o.w = d.w * rstd * s4.w + b4.w;
    reinterpret_cast<float4*>(out)[(size_t)gw * 32 + lane] = o;
}

// ---------------- host orchestration ----------------
extern "C" void kernel_launch(void* const* d_in, const int* in_sizes, int n_in,
                              void* d_out, int out_size) {
    const float* X        = (const float*)d_in[0];
    const int*   idxF     = (const int*)d_in[1];
    const float* wF       = (const float*)d_in[2];
    const int*   idxP     = (const int*)d_in[3];
    const float* wP       = (const float*)d_in[4];
    const float* alpha    = (const float*)d_in[5];
    const float* ip_w     = (const float*)d_in[6];
    const float* ip_b     = (const float*)d_in[7];
    const float* gf_wsrc  = (const float*)d_in[8];
    const float* gf_wdst  = (const float*)d_in[9];
    const float* gf_wedge = (const float*)d_in[10];
    const float* gf_attn  = (const float*)d_in[11];
    const float* gf_bias  = (const float*)d_in[12];
    const float* gp_wsrc  = (const float*)d_in[13];
    const float* gp_wdst  = (const float*)d_in[14];
    const float* gp_wedge = (const float*)d_in[15];
    const float* gp_attn  = (const float*)d_in[16];
    const float* gp_bias  = (const float*)d_in[17];
    const float* ln_scale = (const float*)d_in[18];
    const float* ln_bias  = (const float*)d_in[19];
    float* out = (float*)d_out;

    // CSR build (independent of GEMMs, same stream is fine)
    pack_wcat<<<(128 * 512 + 255) / 256, 256>>>(gf_wsrc, gf_wdst, gp_wsrc, gp_wdst);
    zero_counts<<<(N_CELLS + 255) / 256, 256>>>();
    count_edges<<<(E_FULL + 255) / 256, 256>>>(idxF, E_FULL, 0);
    count_edges<<<(E_PRUNED + 255) / 256, 256>>>(idxP, E_PRUNED, 1);
    scan_counts<<<1, 1024>>>(0);
    scan_counts<<<1, 1024>>>(1);
    scatter_edges<<<(E_FULL + 255) / 256, 256>>>(idxF, E_FULL, 0);
    scatter_edges<<<(E_PRUNED + 255) / 256, 256>>>(idxP, E_PRUNED, 1);

    // h = X @ ip_w + ip_b   -> g_h
    {
        dim3 grid(HIDDEN / 128, (N_CELLS + 127) / 128);
        gemm_f32<<<grid, 256>>>(X, ip_w, ip_b, /*a_sel=*/0, /*b_sel=*/0, /*c_sel=*/0,
                                N_CELLS, HIDDEN, N_GENES);
    }
    // hcat = h @ [wsrcF|wdstF|wsrcP|wdstP]   -> g_hcat
    {
        dim3 grid(512 / 128, (N_CELLS + 127) / 128);
        gemm_f32<<<grid, 256>>>(nullptr, nullptr, nullptr, /*a_sel=*/1, /*b_sel=*/1, /*c_sel=*/1,
                                N_CELLS, 512, HIDDEN);
    }

    // fused aggregation + combine + ELU + LN
    {
        int warps = N_CELLS;
        int threads = 256;
        int blocks = (warps * 32 + threads - 1) / threads;
        gat_finalize<<<blocks, threads>>>(idxF, wF, idxP, wP, alpha,
                                          gf_wedge, gf_attn, gf_bias,
                                          gp_wedge, gp_attn, gp_bias,
                                          ln_scale, ln_bias, out);
    }
}

// round 5
// speedup vs baseline: 1.7362x; 1.7362x over previous
#include <cuda_runtime.h>
#include <cuda_bf16.h>
#include <cstdint>

#define N_CELLS 50000
#define N_GENES 2000
#define HIDDEN 128
#define E_FULL 800000
#define E_PRUNED 400000
#define K1_PAD 2048
#define NC1 64            // K chunks (BK=32) for GEMM1
#define NC2 4             // K chunks for GEMM2
#define BROW 80           // padded SMEM row stride (32 bf16 + 8 pad) bytes
#define TILE_B 10240      // 128 rows * 80 B
#define STAGE_B 40960     // Ah | Al | Bh | Bl
#define SMEM_DYN (2 * STAGE_B)

// ---------------- device scratch (allocation-free) ----------------
__device__ float g_h[(size_t)N_CELLS * HIDDEN];
__device__ float g_hcat[(size_t)N_CELLS * 512];   // [hsF|hdF|hsP|hdP]
__device__ __align__(16) unsigned char g_bt1_hi[(size_t)NC1 * TILE_B];
__device__ __align__(16) unsigned char g_bt1_lo[(size_t)NC1 * TILE_B];
__device__ __align__(16) unsigned char g_bt2_hi[(size_t)4 * NC2 * TILE_B];
__device__ __align__(16) unsigned char g_bt2_lo[(size_t)4 * NC2 * TILE_B];
__device__ int g_cntF[N_CELLS], g_cntP[N_CELLS];
__device__ int g_offF[N_CELLS + 1], g_offP[N_CELLS + 1];
__device__ int g_curF[N_CELLS], g_curP[N_CELLS];
__device__ int g_eidF[E_FULL], g_eidP[E_PRUNED];

// ---------------- helpers ----------------
__device__ __forceinline__ uint32_t smem_u32(const void* p) {
    uint32_t a;
    asm("{ .reg .u64 t; cvta.to.shared.u64 t, %1; cvt.u32.u64 %0, t; }" : "=r"(a) : "l"(p));
    return a;
}
__device__ __forceinline__ void ldsm_x4(uint32_t* r, uint32_t a) {
    asm volatile("ldmatrix.sync.aligned.m8n8.x4.shared.b16 {%0,%1,%2,%3}, [%4];"
                 : "=r"(r[0]), "=r"(r[1]), "=r"(r[2]), "=r"(r[3]) : "r"(a));
}
__device__ __forceinline__ void ldsm_x2(uint32_t* r, uint32_t a) {
    asm volatile("ldmatrix.sync.aligned.m8n8.x2.shared.b16 {%0,%1}, [%2];"
                 : "=r"(r[0]), "=r"(r[1]) : "r"(a));
}
__device__ __forceinline__ void mma_bf16(float* d, const uint32_t* a, const uint32_t* b) {
    asm volatile("mma.sync.aligned.m16n8k16.row.col.f32.bf16.bf16.f32 "
                 "{%0,%1,%2,%3}, {%4,%5,%6,%7}, {%8,%9}, {%0,%1,%2,%3};"
                 : "+f"(d[0]), "+f"(d[1]), "+f"(d[2]), "+f"(d[3])
                 : "r"(a[0]), "r"(a[1]), "r"(a[2]), "r"(a[3]), "r"(b[0]), "r"(b[1]));
}

// ---------------- pack kernels ----------------
// ip_w [2000,128] -> per-chunk padded [n=128][k=32] bf16 hi/lo tiles
__global__ void pack_b1(const float* __restrict__ w) {
    int i = blockIdx.x * blockDim.x + threadIdx.x;
    if (i >= 128 * K1_PAD) return;
    int n = i >> 11;
    int k = i & (K1_PAD - 1);
    float x = (k < N_GENES) ? w[(size_t)k * HIDDEN + n] : 0.f;
    __nv_bfloat16 hb = __float2bfloat16(x);
    __nv_bfloat16 lb = __float2bfloat16(x - __bfloat162float(hb));
    size_t addr = (size_t)(k >> 5) * TILE_B + (size_t)n * BROW + (size_t)(k & 31) * 2;
    *reinterpret_cast<__nv_bfloat16*>(g_bt1_hi + addr) = hb;
    *reinterpret_cast<__nv_bfloat16*>(g_bt1_lo + addr) = lb;
}

// zero counts + pack Bt2 (4 N-tiles x 4 chunks) from 4 [128,128] matrices
__global__ void prep(const float* __restrict__ a, const float* __restrict__ b,
                     const float* __restrict__ c, const float* __restrict__ d) {
    int i = blockIdx.x * blockDim.x + threadIdx.x;
    if (i < N_CELLS) { g_cntF[i] = 0; g_cntP[i] = 0; }
    if (i < 512 * 128) {
        int n = i >> 7, k = i & 127;
        const float* s = (n < 128) ? a : (n < 256) ? b : (n < 384) ? c : d;
        float x = s[(size_t)k * 128 + (n & 127)];
        __nv_bfloat16 hb = __float2bfloat16(x);
        __nv_bfloat16 lb = __float2bfloat16(x - __bfloat162float(hb));
        size_t addr = (size_t)((n >> 7) * NC2 + (k >> 5)) * TILE_B
                    + (size_t)(n & 127) * BROW + (size_t)(k & 31) * 2;
        *reinterpret_cast<__nv_bfloat16*>(g_bt2_hi + addr) = hb;
        *reinterpret_cast<__nv_bfloat16*>(g_bt2_lo + addr) = lb;
    }
}

__global__ void count_both(const int* __restrict__ idxF, const int* __restrict__ idxP) {
    int e = blockIdx.x * blockDim.x + threadIdx.x;
    if (e < E_FULL) {
        atomicAdd(&g_cntF[idxF[E_FULL + e]], 1);
    } else {
        int p = e - E_FULL;
        if (p < E_PRUNED) atomicAdd(&g_cntP[idxP[E_PRUNED + p]], 1);
    }
}

// 1-pass scan: per-thread serial sums + one block scan. 2 blocks (F, P).
__global__ void scan_both() {
    int which = blockIdx.x;
    int* cnt = which ? g_cntP : g_cntF;
    int* off = which ? g_offP : g_offF;
    int* cur = which ? g_curP : g_curF;
    const int PER = 49;
    int t = threadIdx.x;
    int base = t * PER;
    int sum = 0;
    for (int i = 0; i < PER; i++) {
        int idx = base + i;
        if (idx < N_CELLS) sum += cnt[idx];
    }
    __shared__ int sh[1024];
    sh[t] = sum;
    __syncthreads();
    #pragma unroll
    for (int o = 1; o < 1024; o <<= 1) {
        int v = (t >= o) ? sh[t - o] : 0;
        __syncthreads();
        sh[t] += v;
        __syncthreads();
    }
    int run = sh[t] - sum;
    for (int i = 0; i < PER; i++) {
        int idx = base + i;
        if (idx < N_CELLS) {
            off[idx] = run;
            cur[idx] = run;
            run += cnt[idx];
        }
    }
    if (t == 1023) off[N_CELLS] = run;
}

__global__ void scatter_both(const int* __restrict__ idxF, const int* __restrict__ idxP) {
    int e = blockIdx.x * blockDim.x + threadIdx.x;
    if (e < E_FULL) {
        int pos = atomicAdd(&g_curF[idxF[E_FULL + e]], 1);
        g_eidF[pos] = e;
    } else {
        int p = e - E_FULL;
        if (p < E_PRUNED) {
            int pos = atomicAdd(&g_curP[idxP[E_PRUNED + p]], 1);
            g_eidP[pos] = p;
        }
    }
}

// ---------------- mma.sync GEMM: C[M x 128-tile] = A[M,K](fp32) @ Bt(prepacked bf16 hi/lo) ----------------
// fp32 emulation: D += Ah*Bh + Ah*Bl + Al*Bh (bf16 hi/lo split).
__device__ __forceinline__ void load_chunk(const float* __restrict__ A,
                                           const unsigned char* __restrict__ BH,
                                           const unsigned char* __restrict__ BL,
                                           unsigned char* stg, int tid, long rowBase,
                                           int M, int K, int c, size_t bbase) {
    float4 va[4];
    #pragma unroll
    for (int it = 0; it < 4; it++) {
        int slot = tid + it * 256;
        int r = slot >> 3, kq = slot & 7;
        long gr = rowBase + r;
        int kk = c * 32 + kq * 4;
        va[it] = make_float4(0.f, 0.f, 0.f, 0.f);
        if (gr < M && kk < K) va[it] = __ldg(reinterpret_cast<const float4*>(A + gr * (long)K + kk));
    }
    const uint4* bhg = reinterpret_cast<const uint4*>(BH + bbase);
    const uint4* blg = reinterpret_cast<const uint4*>(BL + bbase);
    uint4* sbh = reinterpret_cast<uint4*>(stg + 20480);
    uint4* sbl = reinterpret_cast<uint4*>(stg + 30720);
    for (int j = tid; j < 640; j += 256) {
        sbh[j] = __ldg(bhg + j);
        sbl[j] = __ldg(blg + j);
    }
    #pragma unroll
    for (int it = 0; it < 4; it++) {
        int slot = tid + it * 256;
        int r = slot >> 3, kq = slot & 7;
        float4 v = va[it];
        __nv_bfloat162 h0 = __floats2bfloat162_rn(v.x, v.y);
        __nv_bfloat162 h1 = __floats2bfloat162_rn(v.z, v.w);
        float2 f0 = __bfloat1622float2(h0);
        float2 f1 = __bfloat1622float2(h1);
        __nv_bfloat162 l0 = __floats2bfloat162_rn(v.x - f0.x, v.y - f0.y);
        __nv_bfloat162 l1 = __floats2bfloat162_rn(v.z - f1.x, v.w - f1.y);
        uint32_t off = (uint32_t)r * BROW + (uint32_t)kq * 8;
        *reinterpret_cast<uint2*>(stg + off) =
            make_uint2(*reinterpret_cast<uint32_t*>(&h0), *reinterpret_cast<uint32_t*>(&h1));
        *reinterpret_cast<uint2*>(stg + TILE_B + off) =
            make_uint2(*reinterpret_cast<uint32_t*>(&l0), *reinterpret_cast<uint32_t*>(&l1));
    }
}

__global__ void __launch_bounds__(256, 2) gemm_mma(const float* __restrict__ Aext,
                                                   const float* __restrict__ bias,
                                                   int a_sel, int b_sel, int c_sel,
                                                   int M, int K, int NCols, int NChunks) {
    extern __shared__ unsigned char smp[];
    const float* A = a_sel ? g_h : Aext;
    const unsigned char* BH = b_sel ? g_bt2_hi : g_bt1_hi;
    const unsigned char* BL = b_sel ? g_bt2_lo : g_bt1_lo;
    float* C = c_sel ? g_hcat : g_h;

    int tid = threadIdx.x;
    int lane = tid & 31;
    int wid = tid >> 5;
    int warpM = wid & 1;      // 2 warps along M (64 each)
    int warpN = wid >> 1;     // 4 warps along N (32 each)
    long rowBase = (long)blockIdx.y * 128;
    int nTile = blockIdx.x;
    int colBase = nTile * 128;
    size_t bTileBase = (size_t)nTile * NChunks * TILE_B;

    float acc[4][4][4];
    #pragma unroll
    for (int mi = 0; mi < 4; mi++)
        #pragma unroll
        for (int ni = 0; ni < 4; ni++)
            #pragma unroll
            for (int q = 0; q < 4; q++) acc[mi][ni][q] = 0.f;

    uint32_t sbase0 = smem_u32(smp);
    uint32_t aoff = (uint32_t)(((lane & 7) + ((lane >> 3) & 1) * 8) * BROW + (lane >> 4) * 16);
    uint32_t boff = (uint32_t)((lane & 7) * BROW + ((lane >> 3) & 1) * 16);

    load_chunk(A, BH, BL, smp, tid, rowBase, M, K, 0, bTileBase);

    for (int c = 0; c < NChunks; c++) {
        __syncthreads();
        int nc = c + 1;
        if (nc < NChunks)
            load_chunk(A, BH, BL, smp + (nc & 1) * STAGE_B, tid, rowBase, M, K, nc,
                       bTileBase + (size_t)nc * TILE_B);

        uint32_t sb = sbase0 + (c & 1) * STAGE_B;
        uint32_t sAh = sb, sAl = sb + TILE_B, sBh = sb + 20480, sBl = sb + 30720;
        #pragma unroll
        for (int ks = 0; ks < 2; ks++) {
            uint32_t kb = ks * 32;
            uint32_t ah[4][4], al[4][4], bh[4][2], bl[4][2];
            #pragma unroll
            for (int mi = 0; mi < 4; mi++) {
                uint32_t base = (uint32_t)((warpM * 64 + mi * 16) * BROW) + kb + aoff;
                ldsm_x4(ah[mi], sAh + base);
                ldsm_x4(al[mi], sAl + base);
            }
            #pragma unroll
            for (int ni = 0; ni < 4; ni++) {
                uint32_t base = (uint32_t)((warpN * 32 + ni * 8) * BROW) + kb + boff;
                ldsm_x2(bh[ni], sBh + base);
                ldsm_x2(bl[ni], sBl + base);
            }
            #pragma unroll
            for (int mi = 0; mi < 4; mi++)
                #pragma unroll
                for (int ni = 0; ni < 4; ni++) {
                    mma_bf16(acc[mi][ni], ah[mi], bh[ni]);
                    mma_bf16(acc[mi][ni], ah[mi], bl[ni]);
                    mma_bf16(acc[mi][ni], al[mi], bh[ni]);
                }
        }
    }

    // epilogue: fragment -> GMEM (+bias)
    #pragma unroll
    for (int mi = 0; mi < 4; mi++) {
        #pragma unroll
        for (int ni = 0; ni < 4; ni++) {
            long r0 = rowBase + warpM * 64 + mi * 16 + (lane >> 2);
            int col = colBase + warpN * 32 + ni * 8 + (lane & 3) * 2;
            float b0 = 0.f, b1 = 0.f;
            if (bias) { b0 = __ldg(&bias[col]); b1 = __ldg(&bias[col + 1]); }
            if (r0 < M) {
                float2 v = make_float2(acc[mi][ni][0] + b0, acc[mi][ni][1] + b1);
                *reinterpret_cast<float2*>(C + r0 * (long)NCols + col) = v;
            }
            long r1 = r0 + 8;
            if (r1 < M) {
                float2 v = make_float2(acc[mi][ni][2] + b0, acc[mi][ni][3] + b1);
                *reinterpret_cast<float2*>(C + r1 * (long)NCols + col) = v;
            }
        }
    }
}

// ---------------- fused GAT aggregation (both graphs) + combine + ELU + LayerNorm ----------------
__global__ void __launch_bounds__(256) gat_finalize(
    const int* __restrict__ idxF, const float* __restrict__ wF,
    const int* __restrict__ idxP, const float* __restrict__ wP,
    const float* __restrict__ alpha_p,
    const float* __restrict__ weF, const float* __restrict__ atF, const float* __restrict__ biF,
    const float* __restrict__ weP, const float* __restrict__ atP, const float* __restrict__ biP,
    const float* __restrict__ lnS, const float* __restrict__ lnB,
    float* __restrict__ out) {
    int gw = (blockIdx.x * blockDim.x + threadIdx.x) >> 5;
    int lane = threadIdx.x & 31;
    if (gw >= N_CELLS) return;

    const float4* hc = reinterpret_cast<const float4*>(g_hcat);
    size_t row = (size_t)gw * 128;

    float4 hdF = __ldg(hc + row + 32 + lane);
    float4 hdP = __ldg(hc + row + 96 + lane);
    float4 vweF = __ldg(reinterpret_cast<const float4*>(weF) + lane);
    float4 vatF = __ldg(reinterpret_cast<const float4*>(atF) + lane);
    float4 vweP = __ldg(reinterpret_cast<const float4*>(weP) + lane);
    float4 vatP = __ldg(reinterpret_cast<const float4*>(atP) + lane);

    float4 accF = make_float4(0.f, 0.f, 0.f, 0.f);
    float denF = 0.f;
    {
        int s = g_offF[gw], t = g_offF[gw + 1];
        for (int i = s; i < t; i++) {
            int e = g_eidF[i];
            int src = __ldg(&idxF[e]);
            float we = __ldg(&wF[e]);
            float4 hs = __ldg(hc + (size_t)src * 128 + lane);
            float4 z;
            z.x = fmaf(we, vweF.x, hs.x + hdF.x);
            z.y = fmaf(we, vweF.y, hs.y + hdF.y);
            z.z = fmaf(we, vweF.z, hs.z + hdF.z);
            z.w = fmaf(we, vweF.w, hs.w + hdF.w);
            z.x = fmaxf(z.x, 0.2f * z.x);
            z.y = fmaxf(z.y, 0.2f * z.y);
            z.z = fmaxf(z.z, 0.2f * z.z);
            z.w = fmaxf(z.w, 0.2f * z.w);
            float p = z.x * vatF.x + z.y * vatF.y + z.z * vatF.z + z.w * vatF.w;
            p += __shfl_xor_sync(0xffffffffu, p, 1);
            p += __shfl_xor_sync(0xffffffffu, p, 2);
            p += __shfl_xor_sync(0xffffffffu, p, 4);
            float ex = __expf(p);
            denF += ex;
            accF.x = fmaf(ex, hs.x, accF.x);
            accF.y = fmaf(ex, hs.y, accF.y);
            accF.z = fmaf(ex, hs.z, accF.z);
            accF.w = fmaf(ex, hs.w, accF.w);
        }
    }

    float4 accP = make_float4(0.f, 0.f, 0.f, 0.f);
    float denP = 0.f;
    {
        int s = g_offP[gw], t = g_offP[gw + 1];
        for (int i = s; i < t; i++) {
            int e = g_eidP[i];
            int src = __ldg(&idxP[e]);
            float we = __ldg(&wP[e]);
            float4 hs = __ldg(hc + (size_t)src * 128 + 64 + lane);
            float4 z;
            z.x = fmaf(we, vweP.x, hs.x + hdP.x);
            z.y = fmaf(we, vweP.y, hs.y + hdP.y);
            z.z = fmaf(we, vweP.z, hs.z + hdP.z);
            z.w = fmaf(we, vweP.w, hs.w + hdP.w);
            z.x = fmaxf(z.x, 0.2f * z.x);
            z.y = fmaxf(z.y, 0.2f * z.y);
            z.z = fmaxf(z.z, 0.2f * z.z);
            z.w = fmaxf(z.w, 0.2f * z.w);
            float p = z.x * vatP.x + z.y * vatP.y + z.z * vatP.z + z.w * vatP.w;
            p += __shfl_xor_sync(0xffffffffu, p, 1);
            p += __shfl_xor_sync(0xffffffffu, p, 2);
            p += __shfl_xor_sync(0xffffffffu, p, 4);
            float ex = __expf(p);
            denP += ex;
            accP.x = fmaf(ex, hs.x, accP.x);
            accP.y = fmaf(ex, hs.y, accP.y);
            accP.z = fmaf(ex, hs.z, accP.z);
            accP.w = fmaf(ex, hs.w, accP.w);
        }
    }

    float alpha = __ldg(alpha_p);
    float rdF = 1.f / (denF + 1e-16f);
    float rdP = 1.f / (denP + 1e-16f);
    float4 bF = __ldg(reinterpret_cast<const float4*>(biF) + lane);
    float4 bP = __ldg(reinterpret_cast<const float4*>(biP) + lane);
    float a1 = 1.f - alpha;

    float4 r;
    r.x = a1 * (accF.x * rdF + bF.x) + alpha * (accP.x * rdP + bP.x);
    r.y = a1 * (accF.y * rdF + bF.y) + alpha * (accP.y * rdP + bP.y);
    r.z = a1 * (accF.z * rdF + bF.z) + alpha * (accP.z * rdP + bP.z);
    r.w = a1 * (accF.w * rdF + bF.w) + alpha * (accP.w * rdP + bP.w);

    r.x = r.x > 0.f ? r.x : expm1f(r.x);
    r.y = r.y > 0.f ? r.y : expm1f(r.y);
    r.z = r.z > 0.f ? r.z : expm1f(r.z);
    r.w = r.w > 0.f ? r.w : expm1f(r.w);

    float sum = r.x + r.y + r.z + r.w;
    #pragma unroll
    for (int o = 16; o >= 1; o >>= 1) sum += __shfl_xor_sync(0xffffffffu, sum, o);
    float mu = sum * (1.f / 128.f);
    float4 d;
    d.x = r.x - mu; d.y = r.y - mu; d.z = r.z - mu; d.w = r.w - mu;
    float sq = d.x * d.x + d.y * d.y + d.z * d.z + d.w * d.w;
    #pragma unroll
    for (int o = 16; o >= 1; o >>= 1) sq += __shfl_xor_sync(0xffffffffu, sq, o);
    float rstd = rsqrtf(sq * (1.f / 128.f) + 1e-6f);
    float4 s4 = __ldg(reinterpret_cast<const float4*>(lnS) + lane);
    float4 b4 = __ldg(reinterpret_cast<const float4*>(lnB) + lane);
    float4 o;
    o.x = d.x * rstd * s4.x + b4.x;
    o.y = d.y * rstd * s4.y + b4.y;
    o.z = d.z * rstd * s4.z + b4.z;
    o.w = d.w * rstd * s4.w + b4.w;
    reinterpret_cast<float4*>(out)[(size_t)gw * 32 + lane] = o;
}

// ---------------- host orchestration ----------------
extern "C" void kernel_launch(void* const* d_in, const int* in_sizes, int n_in,
                              void* d_out, int out_size) {
    const float* X        = (const float*)d_in[0];
    const int*   idxF     = (const int*)d_in[1];
    const float* wF       = (const float*)d_in[2];
    const int*   idxP     = (const int*)d_in[3];
    const float* wP       = (const float*)d_in[4];
    const float* alpha    = (const float*)d_in[5];
    const float* ip_w     = (const float*)d_in[6];
    const float* ip_b     = (const float*)d_in[7];
    const float* gf_wsrc  = (const float*)d_in[8];
    const float* gf_wdst  = (const float*)d_in[9];
    const float* gf_wedge = (const float*)d_in[10];
    const float* gf_attn  = (const float*)d_in[11];
    const float* gf_bias  = (const float*)d_in[12];
    const float* gp_wsrc  = (const float*)d_in[13];
    const float* gp_wdst  = (const float*)d_in[14];
    const float* gp_wedge = (const float*)d_in[15];
    const float* gp_attn  = (const float*)d_in[16];
    const float* gp_bias  = (const float*)d_in[17];
    const float* ln_scale = (const float*)d_in[18];
    const float* ln_bias  = (const float*)d_in[19];
    float* out = (float*)d_out;

    cudaFuncSetAttribute(gemm_mma, cudaFuncAttributeMaxDynamicSharedMemorySize, SMEM_DYN);

    // launches ordered so ncu (-s 5 -c 1) profiles gemm_mma GEMM1 (launch #6)
    prep<<<256, 256>>>(gf_wsrc, gf_wdst, gp_wsrc, gp_wdst);                       // 1
    pack_b1<<<(128 * K1_PAD + 255) / 256, 256>>>(ip_w);                           // 2
    count_both<<<(E_FULL + E_PRUNED + 255) / 256, 256>>>(idxF, idxP);             // 3
    scan_both<<<2, 1024>>>();                                                     // 4
    scatter_both<<<(E_FULL + E_PRUNED + 255) / 256, 256>>>(idxF, idxP);           // 5

    // h = X @ ip_w + ip_b  (M=50000, K=2000, Ntile=1)
    gemm_mma<<<dim3(1, (N_CELLS + 127) / 128), 256, SMEM_DYN>>>(
        X, ip_b, 0, 0, 0, N_CELLS, N_GENES, HIDDEN, NC1);                          // 6
    // hcat = h @ [wsrcF|wdstF|wsrcP|wdstP]  (M=50000, K=128, Ntiles=4)
    gemm_mma<<<dim3(4, (N_CELLS + 127) / 128), 256, SMEM_DYN>>>(
        nullptr, nullptr, 1, 1, 1, N_CELLS, HIDDEN, 512, NC2);                     // 7

    gat_finalize<<<(N_CELLS * 32 + 255) / 256, 256>>>(idxF, wF, idxP, wP, alpha,
                                                      gf_wedge, gf_attn, gf_bias,
                                                      gp_wedge, gp_attn, gp_bias,
                                                      ln_scale, ln_bias, out);     // 8
}

// round 6
// speedup vs baseline: 1.9455x; 1.1206x over previous
#include <cuda_runtime.h>
#include <cuda_bf16.h>
#include <cstdint>

#define N_CELLS 50000
#define N_GENES 2000
#define HIDDEN 128
#define E_FULL 800000
#define E_PRUNED 400000
#define K1_PAD 2048
#define NC1 64            // K chunks (BK=32) for GEMM1
#define NC2 4             // K chunks for GEMM2
#define BROW 80           // padded SMEM row stride (32 bf16 + 8 pad) bytes
#define TILE_B 10240      // 128 rows * 80 B
#define STAGE_B 40960     // Ah | Al | Bh | Bl
#define SMEM_DYN (2 * STAGE_B)

// ---------------- device scratch (allocation-free) ----------------
__device__ float g_h[(size_t)N_CELLS * HIDDEN];
__device__ float g_hcat[(size_t)N_CELLS * 512];   // [hsF|hdF|hsP|hdP]
__device__ __align__(16) unsigned char g_bt1_hi[(size_t)NC1 * TILE_B];
__device__ __align__(16) unsigned char g_bt1_lo[(size_t)NC1 * TILE_B];
__device__ __align__(16) unsigned char g_bt2_hi[(size_t)4 * NC2 * TILE_B];
__device__ __align__(16) unsigned char g_bt2_lo[(size_t)4 * NC2 * TILE_B];
__device__ int g_cntF[N_CELLS], g_cntP[N_CELLS];
__device__ int g_offF[N_CELLS], g_offP[N_CELLS];
__device__ int g_curF[N_CELLS], g_curP[N_CELLS];
__device__ int g_totF, g_totP;
__device__ int2 g_epF[E_FULL], g_epP[E_PRUNED];   // (src, weight-bits) in CSR order

// ---------------- helpers ----------------
__device__ __forceinline__ uint32_t smem_u32(const void* p) {
    uint32_t a;
    asm("{ .reg .u64 t; cvta.to.shared.u64 t, %1; cvt.u32.u64 %0, t; }" : "=r"(a) : "l"(p));
    return a;
}
__device__ __forceinline__ void ldsm_x4(uint32_t* r, uint32_t a) {
    asm volatile("ldmatrix.sync.aligned.m8n8.x4.shared.b16 {%0,%1,%2,%3}, [%4];"
                 : "=r"(r[0]), "=r"(r[1]), "=r"(r[2]), "=r"(r[3]) : "r"(a));
}
__device__ __forceinline__ void ldsm_x2(uint32_t* r, uint32_t a) {
    asm volatile("ldmatrix.sync.aligned.m8n8.x2.shared.b16 {%0,%1}, [%2];"
                 : "=r"(r[0]), "=r"(r[1]) : "r"(a));
}
__device__ __forceinline__ void mma_bf16(float* d, const uint32_t* a, const uint32_t* b) {
    asm volatile("mma.sync.aligned.m16n8k16.row.col.f32.bf16.bf16.f32 "
                 "{%0,%1,%2,%3}, {%4,%5,%6,%7}, {%8,%9}, {%0,%1,%2,%3};"
                 : "+f"(d[0]), "+f"(d[1]), "+f"(d[2]), "+f"(d[3])
                 : "r"(a[0]), "r"(a[1]), "r"(a[2]), "r"(a[3]), "r"(b[0]), "r"(b[1]));
}

// ---------------- setup: zero counters + pack B1 + pack B2 ----------------
#define SETUP_B1 (128 * K1_PAD)              // 262144
#define SETUP_B2 (512 * 128)                 // 65536
#define SETUP_TOTAL (SETUP_B1 + SETUP_B2 + N_CELLS)
__global__ void setup(const float* __restrict__ w1,
                      const float* __restrict__ a, const float* __restrict__ b,
                      const float* __restrict__ c, const float* __restrict__ d) {
    int i = blockIdx.x * blockDim.x + threadIdx.x;
    if (i == 0) { g_totF = 0; g_totP = 0; }
    if (i < SETUP_B1) {
        int n = i >> 11;
        int k = i & (K1_PAD - 1);
        float x = (k < N_GENES) ? w1[(size_t)k * HIDDEN + n] : 0.f;
        __nv_bfloat16 hb = __float2bfloat16(x);
        __nv_bfloat16 lb = __float2bfloat16(x - __bfloat162float(hb));
        size_t addr = (size_t)(k >> 5) * TILE_B + (size_t)n * BROW + (size_t)(k & 31) * 2;
        *reinterpret_cast<__nv_bfloat16*>(g_bt1_hi + addr) = hb;
        *reinterpret_cast<__nv_bfloat16*>(g_bt1_lo + addr) = lb;
    } else if (i < SETUP_B1 + SETUP_B2) {
        int j = i - SETUP_B1;
        int n = j >> 7, k = j & 127;
        const float* s = (n < 128) ? a : (n < 256) ? b : (n < 384) ? c : d;
        float x = s[(size_t)k * 128 + (n & 127)];
        __nv_bfloat16 hb = __float2bfloat16(x);
        __nv_bfloat16 lb = __float2bfloat16(x - __bfloat162float(hb));
        size_t addr = (size_t)((n >> 7) * NC2 + (k >> 5)) * TILE_B
                    + (size_t)(n & 127) * BROW + (size_t)(k & 31) * 2;
        *reinterpret_cast<__nv_bfloat16*>(g_bt2_hi + addr) = hb;
        *reinterpret_cast<__nv_bfloat16*>(g_bt2_lo + addr) = lb;
    } else if (i < SETUP_TOTAL) {
        int n = i - SETUP_B1 - SETUP_B2;
        g_cntF[n] = 0;
        g_cntP[n] = 0;
    }
}

__global__ void count_both(const int* __restrict__ idxF, const int* __restrict__ idxP) {
    int e = blockIdx.x * blockDim.x + threadIdx.x;
    if (e < E_FULL) {
        atomicAdd(&g_cntF[idxF[E_FULL + e]], 1);
    } else {
        int p = e - E_FULL;
        if (p < E_PRUNED) atomicAdd(&g_cntP[idxP[E_PRUNED + p]], 1);
    }
}

// offsets via atomic allocation (segment ORDER is irrelevant, only contiguity)
__global__ void assign_off() {
    int i = blockIdx.x * blockDim.x + threadIdx.x;
    if (i >= N_CELLS) return;
    int oF = atomicAdd(&g_totF, g_cntF[i]);
    g_offF[i] = oF;
    g_curF[i] = oF;
    int oP = atomicAdd(&g_totP, g_cntP[i]);
    g_offP[i] = oP;
    g_curP[i] = oP;
}

// scatter (src, weight) pairs into CSR order
__global__ void scatter_both(const int* __restrict__ idxF, const float* __restrict__ wF,
                             const int* __restrict__ idxP, const float* __restrict__ wP) {
    int e = blockIdx.x * blockDim.x + threadIdx.x;
    if (e < E_FULL) {
        int dst = idxF[E_FULL + e];
        int pos = atomicAdd(&g_curF[dst], 1);
        g_epF[pos] = make_int2(idxF[e], __float_as_int(wF[e]));
    } else {
        int p = e - E_FULL;
        if (p < E_PRUNED) {
            int dst = idxP[E_PRUNED + p];
            int pos = atomicAdd(&g_curP[dst], 1);
            g_epP[pos] = make_int2(idxP[p], __float_as_int(wP[p]));
        }
    }
}

// ---------------- mma.sync GEMM: C[M x 128-tile] = A[M,K](fp32) @ Bt(prepacked bf16 hi/lo) ----------------
// fp32 emulation: D += Ah*Bh + Ah*Bl + Al*Bh (bf16 hi/lo split).
__device__ __forceinline__ void load_chunk(const float* __restrict__ A,
                                           const unsigned char* __restrict__ BH,
                                           const unsigned char* __restrict__ BL,
                                           unsigned char* stg, int tid, long rowBase,
                                           int M, int K, int c, size_t bbase) {
    float4 va[4];
    #pragma unroll
    for (int it = 0; it < 4; it++) {
        int slot = tid + it * 256;
        int r = slot >> 3, kq = slot & 7;
        long gr = rowBase + r;
        int kk = c * 32 + kq * 4;
        va[it] = make_float4(0.f, 0.f, 0.f, 0.f);
        if (gr < M && kk < K) va[it] = __ldg(reinterpret_cast<const float4*>(A + gr * (long)K + kk));
    }
    const uint4* bhg = reinterpret_cast<const uint4*>(BH + bbase);
    const uint4* blg = reinterpret_cast<const uint4*>(BL + bbase);
    uint4* sbh = reinterpret_cast<uint4*>(stg + 20480);
    uint4* sbl = reinterpret_cast<uint4*>(stg + 30720);
    for (int j = tid; j < 640; j += 256) {
        sbh[j] = __ldg(bhg + j);
        sbl[j] = __ldg(blg + j);
    }
    #pragma unroll
    for (int it = 0; it < 4; it++) {
        int slot = tid + it * 256;
        int r = slot >> 3, kq = slot & 7;
        float4 v = va[it];
        __nv_bfloat162 h0 = __floats2bfloat162_rn(v.x, v.y);
        __nv_bfloat162 h1 = __floats2bfloat162_rn(v.z, v.w);
        float2 f0 = __bfloat1622float2(h0);
        float2 f1 = __bfloat1622float2(h1);
        __nv_bfloat162 l0 = __floats2bfloat162_rn(v.x - f0.x, v.y - f0.y);
        __nv_bfloat162 l1 = __floats2bfloat162_rn(v.z - f1.x, v.w - f1.y);
        uint32_t off = (uint32_t)r * BROW + (uint32_t)kq * 8;
        *reinterpret_cast<uint2*>(stg + off) =
            make_uint2(*reinterpret_cast<uint32_t*>(&h0), *reinterpret_cast<uint32_t*>(&h1));
        *reinterpret_cast<uint2*>(stg + TILE_B + off) =
            make_uint2(*reinterpret_cast<uint32_t*>(&l0), *reinterpret_cast<uint32_t*>(&l1));
    }
}

__global__ void __launch_bounds__(256, 2) gemm_mma(const float* __restrict__ Aext,
                                                   const float* __restrict__ bias,
                                                   int a_sel, int b_sel, int c_sel,
                                                   int M, int K, int NCols, int NChunks) {
    extern __shared__ unsigned char smp[];
    const float* A = a_sel ? g_h : Aext;
    const unsigned char* BH = b_sel ? g_bt2_hi : g_bt1_hi;
    const unsigned char* BL = b_sel ? g_bt2_lo : g_bt1_lo;
    float* C = c_sel ? g_hcat : g_h;

    int tid = threadIdx.x;
    int lane = tid & 31;
    int wid = tid >> 5;
    int warpM = wid & 1;
    int warpN = wid >> 1;
    long rowBase = (long)blockIdx.y * 128;
    int nTile = blockIdx.x;
    int colBase = nTile * 128;
    size_t bTileBase = (size_t)nTile * NChunks * TILE_B;

    float acc[4][4][4];
    #pragma unroll
    for (int mi = 0; mi < 4; mi++)
        #pragma unroll
        for (int ni = 0; ni < 4; ni++)
            #pragma unroll
            for (int q = 0; q < 4; q++) acc[mi][ni][q] = 0.f;

    uint32_t sbase0 = smem_u32(smp);
    uint32_t aoff = (uint32_t)(((lane & 7) + ((lane >> 3) & 1) * 8) * BROW + (lane >> 4) * 16);
    uint32_t boff = (uint32_t)((lane & 7) * BROW + ((lane >> 3) & 1) * 16);

    load_chunk(A, BH, BL, smp, tid, rowBase, M, K, 0, bTileBase);

    for (int c = 0; c < NChunks; c++) {
        __syncthreads();
        int nc = c + 1;
        if (nc < NChunks)
            load_chunk(A, BH, BL, smp + (nc & 1) * STAGE_B, tid, rowBase, M, K, nc,
                       bTileBase + (size_t)nc * TILE_B);

        uint32_t sb = sbase0 + (c & 1) * STAGE_B;
        uint32_t sAh = sb, sAl = sb + TILE_B, sBh = sb + 20480, sBl = sb + 30720;
        #pragma unroll
        for (int ks = 0; ks < 2; ks++) {
            uint32_t kb = ks * 32;
            uint32_t ah[4][4], al[4][4], bh[4][2], bl[4][2];
            #pragma unroll
            for (int mi = 0; mi < 4; mi++) {
                uint32_t base = (uint32_t)((warpM * 64 + mi * 16) * BROW) + kb + aoff;
                ldsm_x4(ah[mi], sAh + base);
                ldsm_x4(al[mi], sAl + base);
            }
            #pragma unroll
            for (int ni = 0; ni < 4; ni++) {
                uint32_t base = (uint32_t)((warpN * 32 + ni * 8) * BROW) + kb + boff;
                ldsm_x2(bh[ni], sBh + base);
                ldsm_x2(bl[ni], sBl + base);
            }
            #pragma unroll
            for (int mi = 0; mi < 4; mi++)
                #pragma unroll
                for (int ni = 0; ni < 4; ni++) {
                    mma_bf16(acc[mi][ni], ah[mi], bh[ni]);
                    mma_bf16(acc[mi][ni], ah[mi], bl[ni]);
                    mma_bf16(acc[mi][ni], al[mi], bh[ni]);
                }
        }
    }

    #pragma unroll
    for (int mi = 0; mi < 4; mi++) {
        #pragma unroll
        for (int ni = 0; ni < 4; ni++) {
            long r0 = rowBase + warpM * 64 + mi * 16 + (lane >> 2);
            int col = colBase + warpN * 32 + ni * 8 + (lane & 3) * 2;
            float b0 = 0.f, b1 = 0.f;
            if (bias) { b0 = __ldg(&bias[col]); b1 = __ldg(&bias[col + 1]); }
            if (r0 < M) {
                float2 v = make_float2(acc[mi][ni][0] + b0, acc[mi][ni][1] + b1);
                *reinterpret_cast<float2*>(C + r0 * (long)NCols + col) = v;
            }
            long r1 = r0 + 8;
            if (r1 < M) {
                float2 v = make_float2(acc[mi][ni][2] + b0, acc[mi][ni][3] + b1);
                *reinterpret_cast<float2*>(C + r1 * (long)NCols + col) = v;
            }
        }
    }
}

// ---------------- fused GAT aggregation + combine + ELU + LayerNorm ----------------
// One warp per node; F and P edge streams interleaved in one loop (2 indep chains).
__global__ void __launch_bounds__(256) gat_finalize(
    const float* __restrict__ alpha_p,
    const float* __restrict__ weF, const float* __restrict__ atF, const float* __restrict__ biF,
    const float* __restrict__ weP, const float* __restrict__ atP, const float* __restrict__ biP,
    const float* __restrict__ lnS, const float* __restrict__ lnB,
    float* __restrict__ out) {
    int gw = (blockIdx.x * blockDim.x + threadIdx.x) >> 5;
    int lane = threadIdx.x & 31;
    if (gw >= N_CELLS) return;

    const float4* hc = reinterpret_cast<const float4*>(g_hcat);
    size_t row = (size_t)gw * 128;

    float4 hdF = __ldg(hc + row + 32 + lane);
    float4 hdP = __ldg(hc + row + 96 + lane);
    float4 vweF = __ldg(reinterpret_cast<const float4*>(weF) + lane);
    float4 vatF = __ldg(reinterpret_cast<const float4*>(atF) + lane);
    float4 vweP = __ldg(reinterpret_cast<const float4*>(weP) + lane);
    float4 vatP = __ldg(reinterpret_cast<const float4*>(atP) + lane);

    int sF = __ldg(&g_offF[gw]), nF = __ldg(&g_cntF[gw]);
    int sP = __ldg(&g_offP[gw]), nP = __ldg(&g_cntP[gw]);

    float4 accF = make_float4(0.f, 0.f, 0.f, 0.f);
    float4 accP = make_float4(0.f, 0.f, 0.f, 0.f);
    float denF = 0.f, denP = 0.f;

    int nmax = nF > nP ? nF : nP;
    for (int i = 0; i < nmax; i++) {
        if (i < nF) {
            int2 pe = __ldg(&g_epF[sF + i]);
            float we = __int_as_float(pe.y);
            float4 hs = __ldg(hc + (size_t)pe.x * 128 + lane);
            float4 z;
            z.x = fmaf(we, vweF.x, hs.x + hdF.x);
            z.y = fmaf(we, vweF.y, hs.y + hdF.y);
            z.z = fmaf(we, vweF.z, hs.z + hdF.z);
            z.w = fmaf(we, vweF.w, hs.w + hdF.w);
            z.x = fmaxf(z.x, 0.2f * z.x);
            z.y = fmaxf(z.y, 0.2f * z.y);
            z.z = fmaxf(z.z, 0.2f * z.z);
            z.w = fmaxf(z.w, 0.2f * z.w);
            float p = z.x * vatF.x + z.y * vatF.y + z.z * vatF.z + z.w * vatF.w;
            p += __shfl_xor_sync(0xffffffffu, p, 1);
            p += __shfl_xor_sync(0xffffffffu, p, 2);
            p += __shfl_xor_sync(0xffffffffu, p, 4);
            float ex = __expf(p);
            denF += ex;
            accF.x = fmaf(ex, hs.x, accF.x);
            accF.y = fmaf(ex, hs.y, accF.y);
            accF.z = fmaf(ex, hs.z, accF.z);
            accF.w = fmaf(ex, hs.w, accF.w);
        }
        if (i < nP) {
            int2 pe = __ldg(&g_epP[sP + i]);
            float we = __int_as_float(pe.y);
            float4 hs = __ldg(hc + (size_t)pe.x * 128 + 64 + lane);
            float4 z;
            z.x = fmaf(we, vweP.x, hs.x + hdP.x);
            z.y = fmaf(we, vweP.y, hs.y + hdP.y);
            z.z = fmaf(we, vweP.z, hs.z + hdP.z);
            z.w = fmaf(we, vweP.w, hs.w + hdP.w);
            z.x = fmaxf(z.x, 0.2f * z.x);
            z.y = fmaxf(z.y, 0.2f * z.y);
            z.z = fmaxf(z.z, 0.2f * z.z);
            z.w = fmaxf(z.w, 0.2f * z.w);
            float p = z.x * vatP.x + z.y * vatP.y + z.z * vatP.z + z.w * vatP.w;
            p += __shfl_xor_sync(0xffffffffu, p, 1);
            p += __shfl_xor_sync(0xffffffffu, p, 2);
            p += __shfl_xor_sync(0xffffffffu, p, 4);
            float ex = __expf(p);
            denP += ex;
            accP.x = fmaf(ex, hs.x, accP.x);
            accP.y = fmaf(ex, hs.y, accP.y);
            accP.z = fmaf(ex, hs.z, accP.z);
            accP.w = fmaf(ex, hs.w, accP.w);
        }
    }

    float alpha = __ldg(alpha_p);
    float rdF = 1.f / (denF + 1e-16f);
    float rdP = 1.f / (denP + 1e-16f);
    float4 bF = __ldg(reinterpret_cast<const float4*>(biF) + lane);
    float4 bP = __ldg(reinterpret_cast<const float4*>(biP) + lane);
    float a1 = 1.f - alpha;

    float4 r;
    r.x = a1 * (accF.x * rdF + bF.x) + alpha * (accP.x * rdP + bP.x);
    r.y = a1 * (accF.y * rdF + bF.y) + alpha * (accP.y * rdP + bP.y);
    r.z = a1 * (accF.z * rdF + bF.z) + alpha * (accP.z * rdP + bP.z);
    r.w = a1 * (accF.w * rdF + bF.w) + alpha * (accP.w * rdP + bP.w);

    r.x = r.x > 0.f ? r.x : expm1f(r.x);
    r.y = r.y > 0.f ? r.y : expm1f(r.y);
    r.z = r.z > 0.f ? r.z : expm1f(r.z);
    r.w = r.w > 0.f ? r.w : expm1f(r.w);

    float sum = r.x + r.y + r.z + r.w;
    #pragma unroll
    for (int o = 16; o >= 1; o >>= 1) sum += __shfl_xor_sync(0xffffffffu, sum, o);
    float mu = sum * (1.f / 128.f);
    float4 d;
    d.x = r.x - mu; d.y = r.y - mu; d.z = r.z - mu; d.w = r.w - mu;
    float sq = d.x * d.x + d.y * d.y + d.z * d.z + d.w * d.w;
    #pragma unroll
    for (int o = 16; o >= 1; o >>= 1) sq += __shfl_xor_sync(0xffffffffu, sq, o);
    float rstd = rsqrtf(sq * (1.f / 128.f) + 1e-6f);
    float4 s4 = __ldg(reinterpret_cast<const float4*>(lnS) + lane);
    float4 b4 = __ldg(reinterpret_cast<const float4*>(lnB) + lane);
    float4 o;
    o.x = d.x * rstd * s4.x + b4.x;
    o.y = d.y * rstd * s4.y + b4.y;
    o.z = d.z * rstd * s4.z + b4.z;
    o.w = d.w * rstd * s4.w + b4.w;
    reinterpret_cast<float4*>(out)[(size_t)gw * 32 + lane] = o;
}

// ---------------- host orchestration ----------------
extern "C" void kernel_launch(void* const* d_in, const int* in_sizes, int n_in,
                              void* d_out, int out_size) {
    const float* X        = (const float*)d_in[0];
    const int*   idxF     = (const int*)d_in[1];
    const float* wF       = (const float*)d_in[2];
    const int*   idxP     = (const int*)d_in[3];
    const float* wP       = (const float*)d_in[4];
    const float* alpha    = (const float*)d_in[5];
    const float* ip_w     = (const float*)d_in[6];
    const float* ip_b     = (const float*)d_in[7];
    const float* gf_wsrc  = (const float*)d_in[8];
    const float* gf_wdst  = (const float*)d_in[9];
    const float* gf_wedge = (const float*)d_in[10];
    const float* gf_attn  = (const float*)d_in[11];
    const float* gf_bias  = (const float*)d_in[12];
    const float* gp_wsrc  = (const float*)d_in[13];
    const float* gp_wdst  = (const float*)d_in[14];
    const float* gp_wedge = (const float*)d_in[15];
    const float* gp_attn  = (const float*)d_in[16];
    const float* gp_bias  = (const float*)d_in[17];
    const float* ln_scale = (const float*)d_in[18];
    const float* ln_bias  = (const float*)d_in[19];
    float* out = (float*)d_out;

    cudaFuncSetAttribute(gemm_mma, cudaFuncAttributeMaxDynamicSharedMemorySize, SMEM_DYN);

    // launch order: gemm_mma (GEMM1) at position 4 — the slot ncu profiled last round
    setup<<<(SETUP_TOTAL + 255) / 256, 256>>>(ip_w, gf_wsrc, gf_wdst, gp_wsrc, gp_wdst);  // 1
    count_both<<<(E_FULL + E_PRUNED + 255) / 256, 256>>>(idxF, idxP);                     // 2
    assign_off<<<(N_CELLS + 255) / 256, 256>>>();                                         // 3

    // h = X @ ip_w + ip_b  (M=50000, K=2000)
    gemm_mma<<<dim3(1, (N_CELLS + 127) / 128), 256, SMEM_DYN>>>(
        X, ip_b, 0, 0, 0, N_CELLS, N_GENES, HIDDEN, NC1);                                 // 4
    // hcat = h @ [wsrcF|wdstF|wsrcP|wdstP]  (M=50000, K=128, Ntiles=4)
    gemm_mma<<<dim3(4, (N_CELLS + 127) / 128), 256, SMEM_DYN>>>(
        nullptr, nullptr, 1, 1, 1, N_CELLS, HIDDEN, 512, NC2);                            // 5

    scatter_both<<<(E_FULL + E_PRUNED + 255) / 256, 256>>>(idxF, wF, idxP, wP);           // 6

    gat_finalize<<<(N_CELLS * 32 + 255) / 256, 256>>>(alpha,
                                                      gf_wedge, gf_attn, gf_bias,
                                                      gp_wedge, gp_attn, gp_bias,
                                                      ln_scale, ln_bias, out);            // 7
}